// round 1
// baseline (speedup 1.0000x reference)
#include <cuda_runtime.h>
#include <math.h>

// ---------------------------------------------------------------------------
// Problem constants
// ---------------------------------------------------------------------------
constexpr int B    = 4;
constexpr int N    = 2048;
constexpr int D    = 1024;
constexpr int E    = 24;
constexpr int H    = 8;
constexpr int HD   = 128;
constexpr int BN_TOK = B * N;          // 8192 tokens

// ---------------------------------------------------------------------------
// Scratch (device globals — no allocations allowed)
// ---------------------------------------------------------------------------
__device__ float g_k[BN_TOK * HD];             // 4 MB
__device__ float g_v[BN_TOK * HD];             // 4 MB
__device__ float g_q[BN_TOK * H * HD];         // 32 MB
__device__ float g_attno[BN_TOK * H * HD];     // 32 MB
__device__ int   g_topi[BN_TOK * H];
__device__ float g_gates[BN_TOK * H];
__device__ float g_aux[2 * E + 1];             // [0,E): freq counts, [E,2E): pmean sums, [2E]: sum lse^2

// ---------------------------------------------------------------------------
// Kernel 0: zero aux accumulators
// ---------------------------------------------------------------------------
__global__ void init_aux_kernel() {
    if (threadIdx.x < 2 * E + 1) g_aux[threadIdx.x] = 0.f;
}

// ---------------------------------------------------------------------------
// Kernel 1: gating — logits, softmax, top-8, gates, aux partials
// one warp per token, 8 warps per block
// ---------------------------------------------------------------------------
__global__ __launch_bounds__(256) void gating_kernel(
    const float* __restrict__ x, const int* __restrict__ task_bh,
    const float* __restrict__ Wg)
{
    __shared__ float s_aux[2 * E + 1];
    int tid = threadIdx.x;
    if (tid < 2 * E + 1) s_aux[tid] = 0.f;
    __syncthreads();

    int warp = tid >> 5, lane = tid & 31;
    int t = blockIdx.x * 8 + warp;
    int b = t >> 11;                      // N = 2048
    int task = task_bh[b];
    const float* xrow = x + (size_t)t * D;
    const float* wg   = Wg + (size_t)task * D * E;

    float acc[E];
#pragma unroll
    for (int e = 0; e < E; e++) acc[e] = 0.f;

    for (int i = lane; i < D; i += 32) {
        float xv = xrow[i];
        const float4* w4 = reinterpret_cast<const float4*>(wg + (size_t)i * E);
#pragma unroll
        for (int j = 0; j < 6; j++) {
            float4 v = w4[j];
            acc[4*j+0] += xv * v.x; acc[4*j+1] += xv * v.y;
            acc[4*j+2] += xv * v.z; acc[4*j+3] += xv * v.w;
        }
    }
#pragma unroll
    for (int e = 0; e < E; e++) {
#pragma unroll
        for (int off = 16; off >= 1; off >>= 1)
            acc[e] += __shfl_xor_sync(0xffffffffu, acc[e], off);
    }
    // every lane now holds all 24 logits
    float mx = acc[0];
#pragma unroll
    for (int e = 1; e < E; e++) mx = fmaxf(mx, acc[e]);
    float p[E]; float s = 0.f;
#pragma unroll
    for (int e = 0; e < E; e++) { p[e] = __expf(acc[e] - mx); s += p[e]; }
    float inv_s = 1.f / s;
    float lse = mx + __logf(s);

    if (lane < E) atomicAdd(&s_aux[E + lane], p[lane] * inv_s);
    if (lane == 0) {
        atomicAdd(&s_aux[2 * E], lse * lse);
        float tv[H]; int ti[H]; float gsum = 0.f;
#pragma unroll
        for (int h = 0; h < H; h++) {
            float best = -1.f; int bi = 0;
#pragma unroll
            for (int e = 0; e < E; e++)
                if (p[e] > best) { best = p[e]; bi = e; }
            tv[h] = best * inv_s; ti[h] = bi; p[bi] = -2.f;
            gsum += tv[h];
            atomicAdd(&s_aux[bi], 1.0f);
        }
        float ig = 1.f / gsum;
#pragma unroll
        for (int h = 0; h < H; h++) {
            g_topi[t * H + h]  = ti[h];
            g_gates[t * H + h] = tv[h] * ig;
        }
    }
    __syncthreads();
    if (tid < 2 * E + 1) atomicAdd(&g_aux[tid], s_aux[tid]);
}

// ---------------------------------------------------------------------------
// Kernel 2: kv = x @ Wkv + bkv  → split into g_k, g_v
// tiled GEMM: 64x64 tile, 4x4 per thread, BK=16
// ---------------------------------------------------------------------------
__global__ __launch_bounds__(256) void kv_kernel(
    const float* __restrict__ x, const float* __restrict__ Wkv,
    const float* __restrict__ bkv)
{
    __shared__ float As[64][17];
    __shared__ float Bs[16][64];
    int tid = threadIdx.x;
    int tx = tid & 15, ty = tid >> 4;
    int t0 = blockIdx.x * 64;
    int n0 = blockIdx.y * 64;

    float acc[4][4] = {};

    for (int k0 = 0; k0 < D; k0 += 16) {
#pragma unroll
        for (int i = 0; i < 4; i++) {
            int idx = tid + i * 256;
            int r = idx >> 4, kk = idx & 15;
            As[r][kk] = x[(size_t)(t0 + r) * D + k0 + kk];
        }
#pragma unroll
        for (int i = 0; i < 4; i++) {
            int idx = tid + i * 256;
            int kr = idx >> 6, nn = idx & 63;
            Bs[kr][nn] = Wkv[(size_t)(k0 + kr) * (2 * HD) + n0 + nn];
        }
        __syncthreads();
#pragma unroll
        for (int kk = 0; kk < 16; kk++) {
            float a[4];
#pragma unroll
            for (int i = 0; i < 4; i++) a[i] = As[ty * 4 + i][kk];
            float4 bv = *reinterpret_cast<const float4*>(&Bs[kk][tx * 4]);
            float bb[4] = {bv.x, bv.y, bv.z, bv.w};
#pragma unroll
            for (int i = 0; i < 4; i++)
#pragma unroll
                for (int j = 0; j < 4; j++)
                    acc[i][j] += a[i] * bb[j];
        }
        __syncthreads();
    }
#pragma unroll
    for (int i = 0; i < 4; i++) {
        int t = t0 + ty * 4 + i;
#pragma unroll
        for (int j = 0; j < 4; j++) {
            int c = n0 + tx * 4 + j;
            float v = acc[i][j] + bkv[c];
            if (c < HD) g_k[(size_t)t * HD + c] = v;
            else        g_v[(size_t)t * HD + (c - HD)] = v;
        }
    }
}

// ---------------------------------------------------------------------------
// Kernel 3: gathered q — per 16-token tile, group (token,slot) by expert
// warps process experts independently; 8 slots per weight pass
// ---------------------------------------------------------------------------
constexpr int QTW = 16;
constexpr int XS_STRIDE = 1028;   // 1024 + 4 pad: bank = (4*tok + k) % 32

__global__ __launch_bounds__(256) void q_kernel(
    const float* __restrict__ x, const float* __restrict__ Wq)
{
    extern __shared__ float sm[];
    float* xs   = sm;                                 // QTW * 1028
    int*   ecnt = (int*)(xs + QTW * XS_STRIDE);       // E
    int*   elist = ecnt + E;                          // E * QTW

    int tid = threadIdx.x;
    int token0 = blockIdx.x * QTW;
    if (tid < E) ecnt[tid] = 0;
    __syncthreads();

    for (int idx = tid; idx < QTW * (D / 4); idx += 256) {
        int tok = idx >> 8;            // D/4 = 256
        int kq  = idx & 255;
        *reinterpret_cast<float4*>(xs + tok * XS_STRIDE + kq * 4) =
            *reinterpret_cast<const float4*>(x + (size_t)(token0 + tok) * D + kq * 4);
    }
    if (tid < QTW * H) {
        int e = g_topi[token0 * H + tid];
        int pos = atomicAdd(&ecnt[e], 1);
        elist[e * QTW + pos] = tid;    // slot id = tok_local*8 + h
    }
    __syncthreads();

    int warp = tid >> 5, lane = tid & 31;
    int d0 = lane * 4;

    for (int e = warp; e < E; e += 8) {
        int cnt = ecnt[e];
        const float* wq = Wq + (size_t)e * D * HD;
        for (int base = 0; base < cnt; base += 8) {
            int nsl = min(8, cnt - base);
            int slot[8]; int xoff[8];
#pragma unroll
            for (int j = 0; j < 8; j++) {
                int s = elist[e * QTW + base + (j < nsl ? j : 0)];
                slot[j] = s;
                xoff[j] = (s >> 3) * XS_STRIDE;
            }
            float acc[8][4] = {};
#pragma unroll 4
            for (int k = 0; k < D; k++) {
                float4 w = *reinterpret_cast<const float4*>(wq + (size_t)k * HD + d0);
#pragma unroll
                for (int j = 0; j < 8; j++) {
                    float xv = xs[xoff[j] + k];
                    acc[j][0] += xv * w.x; acc[j][1] += xv * w.y;
                    acc[j][2] += xv * w.z; acc[j][3] += xv * w.w;
                }
            }
            for (int j = 0; j < nsl; j++) {
                int s = slot[j];
                int gt = token0 + (s >> 3);
                int h  = s & 7;
                float4 o = make_float4(acc[j][0], acc[j][1], acc[j][2], acc[j][3]);
                *reinterpret_cast<float4*>(g_q + (((size_t)gt * H + h) * HD) + d0) = o;
            }
        }
    }
}

// ---------------------------------------------------------------------------
// Kernel 4: flash-style MQA attention (fp32)
// block = (n-tile of 64, head h, batch b); 16x16 threads, 4x4 S-fragment,
// 4x8 O-fragment. Qs/Ks transposed in smem for float4 fragment loads.
// ---------------------------------------------------------------------------
__global__ __launch_bounds__(256) void attn_kernel()
{
    extern __shared__ float sm[];
    float* Qs = sm;                    // [128][68]  Q^T
    float* Ks = Qs + 128 * 68;         // [128][68]  K^T
    float* Vs = Ks + 128 * 68;         // [64][132]  V
    float* Ps = Vs + 64 * 132;         // [64][68]   P

    int tid = threadIdx.x;
    int tx = tid & 15, ty = tid >> 4;
    int n0 = blockIdx.x * 64;
    int h  = blockIdx.y;
    int b  = blockIdx.z;
    const float scale = 0.08838834764831845f;   // 1/sqrt(128)

    // load Q^T (once)
    for (int idx = tid; idx < 64 * 128; idx += 256) {
        int r = idx >> 7, k = idx & 127;
        Qs[k * 68 + r] = g_q[(((size_t)(b * N + n0 + r)) * H + h) * HD + k];
    }

    float m_i[4], l_i[4], o[4][8];
#pragma unroll
    for (int i = 0; i < 4; i++) {
        m_i[i] = -1e30f; l_i[i] = 0.f;
#pragma unroll
        for (int j = 0; j < 8; j++) o[i][j] = 0.f;
    }

    for (int m0 = 0; m0 < N; m0 += 64) {
        __syncthreads();  // previous tile fully consumed (also covers Q load)
        for (int idx = tid; idx < 64 * 128; idx += 256) {
            int ml = idx >> 7, k = idx & 127;
            Ks[k * 68 + ml] = g_k[((size_t)(b * N + m0 + ml)) * HD + k];
        }
        for (int idx = tid; idx < 64 * 32; idx += 256) {
            int ml = idx >> 5, kq = (idx & 31) << 2;
            *reinterpret_cast<float4*>(Vs + ml * 132 + kq) =
                *reinterpret_cast<const float4*>(g_v + ((size_t)(b * N + m0 + ml)) * HD + kq);
        }
        __syncthreads();

        // S = Q K^T
        float sacc[4][4] = {};
#pragma unroll 8
        for (int k = 0; k < 128; k++) {
            float4 qf = *reinterpret_cast<const float4*>(Qs + k * 68 + ty * 4);
            float4 kf = *reinterpret_cast<const float4*>(Ks + k * 68 + tx * 4);
            float qa[4] = {qf.x, qf.y, qf.z, qf.w};
            float ka[4] = {kf.x, kf.y, kf.z, kf.w};
#pragma unroll
            for (int i = 0; i < 4; i++)
#pragma unroll
                for (int j = 0; j < 4; j++)
                    sacc[i][j] += qa[i] * ka[j];
        }

        // online softmax update
#pragma unroll
        for (int i = 0; i < 4; i++) {
            float rm = fmaxf(fmaxf(sacc[i][0], sacc[i][1]),
                             fmaxf(sacc[i][2], sacc[i][3])) * scale;
#pragma unroll
            for (int off = 8; off >= 1; off >>= 1)
                rm = fmaxf(rm, __shfl_xor_sync(0xffffffffu, rm, off));
            float mnew = fmaxf(m_i[i], rm);
            float alpha = __expf(m_i[i] - mnew);
            m_i[i] = mnew;
            float rs = 0.f;
#pragma unroll
            for (int j = 0; j < 4; j++) {
                float pv = __expf(sacc[i][j] * scale - mnew);
                Ps[(ty * 4 + i) * 68 + tx * 4 + j] = pv;
                rs += pv;
            }
#pragma unroll
            for (int off = 8; off >= 1; off >>= 1)
                rs += __shfl_xor_sync(0xffffffffu, rs, off);
            l_i[i] = l_i[i] * alpha + rs;
#pragma unroll
            for (int j = 0; j < 8; j++) o[i][j] *= alpha;
        }
        __syncthreads();

        // O += P V
#pragma unroll 4
        for (int mm = 0; mm < 64; mm++) {
            float4 va = *reinterpret_cast<const float4*>(Vs + mm * 132 + tx * 4);
            float4 vb = *reinterpret_cast<const float4*>(Vs + mm * 132 + tx * 4 + 64);
#pragma unroll
            for (int i = 0; i < 4; i++) {
                float pv = Ps[(ty * 4 + i) * 68 + mm];
                o[i][0] += pv * va.x; o[i][1] += pv * va.y;
                o[i][2] += pv * va.z; o[i][3] += pv * va.w;
                o[i][4] += pv * vb.x; o[i][5] += pv * vb.y;
                o[i][6] += pv * vb.z; o[i][7] += pv * vb.w;
            }
        }
    }

#pragma unroll
    for (int i = 0; i < 4; i++) {
        float inv = 1.f / l_i[i];
        int gt = b * N + n0 + ty * 4 + i;
        float* dst = g_attno + ((size_t)gt * H + h) * HD;
        float4 oa = make_float4(o[i][0]*inv, o[i][1]*inv, o[i][2]*inv, o[i][3]*inv);
        float4 ob = make_float4(o[i][4]*inv, o[i][5]*inv, o[i][6]*inv, o[i][7]*inv);
        *reinterpret_cast<float4*>(dst + tx * 4)      = oa;
        *reinterpret_cast<float4*>(dst + tx * 4 + 64) = ob;
    }
}

// ---------------------------------------------------------------------------
// Kernel 5: combine — y[token] = sum_h gate_h * (attn_out_h @ Wo[e_h])
// 16-token tile; block-wide per-expert passes; thread owns 4 y-columns
// ---------------------------------------------------------------------------
constexpr int CTW = 16;

__global__ __launch_bounds__(256) void combine_kernel(
    const float* __restrict__ Wo, float* __restrict__ y)
{
    extern __shared__ float sm[];
    float* outs    = sm;                          // [128][132]
    float* ys      = outs + 128 * 132;            // [16][1024]
    float* gates_s = ys + CTW * D;                // 128
    int*   ecnt    = (int*)(gates_s + 128);       // E
    int*   elist   = ecnt + E;                    // E * 16

    int tid = threadIdx.x;
    int token0 = blockIdx.x * CTW;
    if (tid < E) ecnt[tid] = 0;
    __syncthreads();

    if (tid < CTW * H) {
        gates_s[tid] = g_gates[token0 * H + tid];
        int e = g_topi[token0 * H + tid];
        int pos = atomicAdd(&ecnt[e], 1);
        elist[e * CTW + pos] = tid;
    }
    for (int idx = tid; idx < 128 * 32; idx += 256) {
        int s = idx >> 5, kq = (idx & 31) << 2;
        *reinterpret_cast<float4*>(outs + s * 132 + kq) =
            *reinterpret_cast<const float4*>(g_attno + ((size_t)token0 * H + s) * HD + kq);
    }
    for (int idx = tid; idx < CTW * D; idx += 256) ys[idx] = 0.f;
    __syncthreads();

    int c0 = tid * 4;
    for (int e = 0; e < E; e++) {
        int cnt = ecnt[e];
        if (cnt == 0) continue;
        const float* wo = Wo + (size_t)e * HD * D;
        for (int base = 0; base < cnt; base += 8) {
            int nsl = min(8, cnt - base);
            int slot[8]; int soff[8];
#pragma unroll
            for (int j = 0; j < 8; j++) {
                int s = elist[e * CTW + base + (j < nsl ? j : 0)];
                slot[j] = s;
                soff[j] = s * 132;
            }
            float acc[8][4] = {};
#pragma unroll 4
            for (int k = 0; k < HD; k++) {
                float4 w = *reinterpret_cast<const float4*>(wo + (size_t)k * D + c0);
#pragma unroll
                for (int j = 0; j < 8; j++) {
                    float a = outs[soff[j] + k];
                    acc[j][0] += a * w.x; acc[j][1] += a * w.y;
                    acc[j][2] += a * w.z; acc[j][3] += a * w.w;
                }
            }
            for (int j = 0; j < nsl; j++) {
                int s = slot[j];
                float g = gates_s[s];
                float* yp = ys + (s >> 3) * D + c0;
                yp[0] += g * acc[j][0]; yp[1] += g * acc[j][1];
                yp[2] += g * acc[j][2]; yp[3] += g * acc[j][3];
            }
        }
    }
    __syncthreads();

    for (int idx = tid; idx < CTW * (D / 4); idx += 256) {
        int tok = idx >> 8, cq = (idx & 255) << 2;
        *reinterpret_cast<float4*>(y + (size_t)(token0 + tok) * D + cq) =
            *reinterpret_cast<const float4*>(ys + tok * D + cq);
    }
}

// ---------------------------------------------------------------------------
// Kernel 6: finalize aux loss
// ---------------------------------------------------------------------------
__global__ void aux_final_kernel(float* __restrict__ out) {
    if (threadIdx.x == 0) {
        const float inv_bn = 1.0f / (float)BN_TOK;
        float sw = 0.f;
        for (int e = 0; e < E; e++)
            sw += (g_aux[e] * inv_bn) * (g_aux[E + e] * inv_bn);
        float aux = 0.1f * (float)E * sw + 0.001f * (g_aux[2 * E] * inv_bn);
        out[(size_t)BN_TOK * D] = aux;
    }
}

// ---------------------------------------------------------------------------
// Launch
// ---------------------------------------------------------------------------
extern "C" void kernel_launch(void* const* d_in, const int* in_sizes, int n_in,
                              void* d_out, int out_size)
{
    const float* x    = (const float*)d_in[0];
    const int* task_bh = (const int*)d_in[1];
    const float* Wg   = (const float*)d_in[2];
    const float* Wq   = (const float*)d_in[3];
    const float* Wo   = (const float*)d_in[4];
    const float* Wkv  = (const float*)d_in[5];
    const float* bkv  = (const float*)d_in[6];
    float* out = (float*)d_out;

    const int q_smem    = (QTW * XS_STRIDE) * 4 + (E + E * QTW) * 4;
    const int attn_smem = (128 * 68 + 128 * 68 + 64 * 132 + 64 * 68) * 4;
    const int comb_smem = (128 * 132 + CTW * D + 128) * 4 + (E + E * CTW) * 4;

    cudaFuncSetAttribute(q_kernel,       cudaFuncAttributeMaxDynamicSharedMemorySize, q_smem);
    cudaFuncSetAttribute(attn_kernel,    cudaFuncAttributeMaxDynamicSharedMemorySize, attn_smem);
    cudaFuncSetAttribute(combine_kernel, cudaFuncAttributeMaxDynamicSharedMemorySize, comb_smem);

    init_aux_kernel<<<1, 64>>>();
    gating_kernel<<<BN_TOK / 8, 256>>>(x, task_bh, Wg);
    kv_kernel<<<dim3(BN_TOK / 64, (2 * HD) / 64), 256>>>(x, Wkv, bkv);
    q_kernel<<<BN_TOK / QTW, 256, q_smem>>>(x, Wq);
    attn_kernel<<<dim3(N / 64, H, B), 256, attn_smem>>>();
    combine_kernel<<<BN_TOK / CTW, 256, comb_smem>>>(Wo, out);
    aux_final_kernel<<<1, 32>>>(out);
}

// round 3
// speedup vs baseline: 1.2166x; 1.2166x over previous
#include <cuda_runtime.h>
#include <math.h>
#include <stdint.h>

// ---------------------------------------------------------------------------
// Problem constants
// ---------------------------------------------------------------------------
constexpr int B    = 4;
constexpr int N    = 2048;
constexpr int D    = 1024;
constexpr int E    = 24;
constexpr int H    = 8;
constexpr int HD   = 128;
constexpr int BN_TOK = B * N;          // 8192 tokens

// ---------------------------------------------------------------------------
// Scratch (device globals — no allocations allowed)
// ---------------------------------------------------------------------------
__device__ float g_kT[HD * BN_TOK];            // 4 MB  K^T: [hd][token]
__device__ float g_v[BN_TOK * HD];             // 4 MB
__device__ float g_q[BN_TOK * H * HD];         // 32 MB
__device__ float g_attno[BN_TOK * H * HD];     // 32 MB
__device__ int   g_topi[BN_TOK * H];
__device__ float g_gates[BN_TOK * H];
__device__ float g_aux[2 * E + 1];

// ---------------------------------------------------------------------------
// tf32 mma helpers (3xTF32 error-compensated path)
// ---------------------------------------------------------------------------
__device__ __forceinline__ void mma_tf32(float* d, const uint32_t* a, const uint32_t* b) {
    asm volatile(
        "mma.sync.aligned.m16n8k8.row.col.f32.tf32.tf32.f32 "
        "{%0,%1,%2,%3}, {%4,%5,%6,%7}, {%8,%9}, {%0,%1,%2,%3};\n"
        : "+f"(d[0]), "+f"(d[1]), "+f"(d[2]), "+f"(d[3])
        : "r"(a[0]), "r"(a[1]), "r"(a[2]), "r"(a[3]), "r"(b[0]), "r"(b[1]));
}
__device__ __forceinline__ uint32_t fu(float x) { return __float_as_uint(x); }
__device__ __forceinline__ float tf32_hi(float x) {
    uint32_t u;
    asm("cvt.rna.tf32.f32 %0, %1;" : "=r"(u) : "f"(x));
    return __uint_as_float(u);
}
// split 4-vector a into hi/lo tf32 fragments
__device__ __forceinline__ void split4(const float* a, uint32_t* ah, uint32_t* al) {
#pragma unroll
    for (int j = 0; j < 4; j++) {
        float h = tf32_hi(a[j]);
        ah[j] = fu(h);
        al[j] = fu(a[j] - h);
    }
}
__device__ __forceinline__ void split2(float b0, float b1, uint32_t* bh, uint32_t* bl) {
    float h0 = tf32_hi(b0), h1 = tf32_hi(b1);
    bh[0] = fu(h0); bh[1] = fu(h1);
    bl[0] = fu(b0 - h0); bl[1] = fu(b1 - h1);
}
// d += a*b with 3xtf32 compensation
__device__ __forceinline__ void mma3(float* d, const uint32_t* ah, const uint32_t* al,
                                     const uint32_t* bh, const uint32_t* bl) {
    mma_tf32(d, al, bh);
    mma_tf32(d, ah, bl);
    mma_tf32(d, ah, bh);
}

// ---------------------------------------------------------------------------
// Kernel 0: zero aux accumulators
// ---------------------------------------------------------------------------
__global__ void init_aux_kernel() {
    if (threadIdx.x < 2 * E + 1) g_aux[threadIdx.x] = 0.f;
}

// ---------------------------------------------------------------------------
// Kernel 1: gating
// ---------------------------------------------------------------------------
__global__ __launch_bounds__(256) void gating_kernel(
    const float* __restrict__ x, const int* __restrict__ task_bh,
    const float* __restrict__ Wg)
{
    __shared__ float s_aux[2 * E + 1];
    int tid = threadIdx.x;
    if (tid < 2 * E + 1) s_aux[tid] = 0.f;
    __syncthreads();

    int warp = tid >> 5, lane = tid & 31;
    int t = blockIdx.x * 8 + warp;
    int b = t >> 11;
    int task = task_bh[b];
    const float* xrow = x + (size_t)t * D;
    const float* wg   = Wg + (size_t)task * D * E;

    float acc[E];
#pragma unroll
    for (int e = 0; e < E; e++) acc[e] = 0.f;

    for (int i = lane; i < D; i += 32) {
        float xv = xrow[i];
        const float4* w4 = reinterpret_cast<const float4*>(wg + (size_t)i * E);
#pragma unroll
        for (int j = 0; j < 6; j++) {
            float4 v = w4[j];
            acc[4*j+0] += xv * v.x; acc[4*j+1] += xv * v.y;
            acc[4*j+2] += xv * v.z; acc[4*j+3] += xv * v.w;
        }
    }
#pragma unroll
    for (int e = 0; e < E; e++) {
#pragma unroll
        for (int off = 16; off >= 1; off >>= 1)
            acc[e] += __shfl_xor_sync(0xffffffffu, acc[e], off);
    }
    float mx = acc[0];
#pragma unroll
    for (int e = 1; e < E; e++) mx = fmaxf(mx, acc[e]);
    float p[E]; float s = 0.f;
#pragma unroll
    for (int e = 0; e < E; e++) { p[e] = __expf(acc[e] - mx); s += p[e]; }
    float inv_s = 1.f / s;
    float lse = mx + __logf(s);

    if (lane < E) atomicAdd(&s_aux[E + lane], p[lane] * inv_s);
    if (lane == 0) {
        atomicAdd(&s_aux[2 * E], lse * lse);
        float tv[H]; int ti[H]; float gsum = 0.f;
#pragma unroll
        for (int h = 0; h < H; h++) {
            float best = -1.f; int bi = 0;
#pragma unroll
            for (int e = 0; e < E; e++)
                if (p[e] > best) { best = p[e]; bi = e; }
            tv[h] = best * inv_s; ti[h] = bi; p[bi] = -2.f;
            gsum += tv[h];
            atomicAdd(&s_aux[bi], 1.0f);
        }
        float ig = 1.f / gsum;
#pragma unroll
        for (int h = 0; h < H; h++) {
            g_topi[t * H + h]  = ti[h];
            g_gates[t * H + h] = tv[h] * ig;
        }
    }
    __syncthreads();
    if (tid < 2 * E + 1) atomicAdd(&g_aux[tid], s_aux[tid]);
}

// ---------------------------------------------------------------------------
// Kernel 2: kv = x @ Wkv + bkv  → g_kT (transposed), g_v
// ---------------------------------------------------------------------------
__global__ __launch_bounds__(256) void kv_kernel(
    const float* __restrict__ x, const float* __restrict__ Wkv,
    const float* __restrict__ bkv)
{
    __shared__ float As[64][17];
    __shared__ float Bs[16][64];
    int tid = threadIdx.x;
    int tx = tid & 15, ty = tid >> 4;
    int t0 = blockIdx.x * 64;
    int n0 = blockIdx.y * 64;

    float acc[4][4] = {};

    for (int k0 = 0; k0 < D; k0 += 16) {
#pragma unroll
        for (int i = 0; i < 4; i++) {
            int idx = tid + i * 256;
            int r = idx >> 4, kk = idx & 15;
            As[r][kk] = x[(size_t)(t0 + r) * D + k0 + kk];
        }
#pragma unroll
        for (int i = 0; i < 4; i++) {
            int idx = tid + i * 256;
            int kr = idx >> 6, nn = idx & 63;
            Bs[kr][nn] = Wkv[(size_t)(k0 + kr) * (2 * HD) + n0 + nn];
        }
        __syncthreads();
#pragma unroll
        for (int kk = 0; kk < 16; kk++) {
            float a[4];
#pragma unroll
            for (int i = 0; i < 4; i++) a[i] = As[ty * 4 + i][kk];
            float4 bv = *reinterpret_cast<const float4*>(&Bs[kk][tx * 4]);
            float bb[4] = {bv.x, bv.y, bv.z, bv.w};
#pragma unroll
            for (int i = 0; i < 4; i++)
#pragma unroll
                for (int j = 0; j < 4; j++)
                    acc[i][j] += a[i] * bb[j];
        }
        __syncthreads();
    }
#pragma unroll
    for (int i = 0; i < 4; i++) {
        int t = t0 + ty * 4 + i;
#pragma unroll
        for (int j = 0; j < 4; j++) {
            int c = n0 + tx * 4 + j;
            float v = acc[i][j] + bkv[c];
            if (c < HD) g_kT[(size_t)c * BN_TOK + t] = v;
            else        g_v[(size_t)t * HD + (c - HD)] = v;
        }
    }
}

// ---------------------------------------------------------------------------
// Kernel 3: gathered q projection
// ---------------------------------------------------------------------------
constexpr int QTW = 16;
constexpr int XS_STRIDE = 1028;

__global__ __launch_bounds__(256) void q_kernel(
    const float* __restrict__ x, const float* __restrict__ Wq)
{
    extern __shared__ float sm[];
    float* xs   = sm;
    int*   ecnt = (int*)(xs + QTW * XS_STRIDE);
    int*   elist = ecnt + E;

    int tid = threadIdx.x;
    int token0 = blockIdx.x * QTW;
    if (tid < E) ecnt[tid] = 0;
    __syncthreads();

    for (int idx = tid; idx < QTW * (D / 4); idx += 256) {
        int tok = idx >> 8;
        int kq  = idx & 255;
        *reinterpret_cast<float4*>(xs + tok * XS_STRIDE + kq * 4) =
            *reinterpret_cast<const float4*>(x + (size_t)(token0 + tok) * D + kq * 4);
    }
    if (tid < QTW * H) {
        int e = g_topi[token0 * H + tid];
        int pos = atomicAdd(&ecnt[e], 1);
        elist[e * QTW + pos] = tid;
    }
    __syncthreads();

    int warp = tid >> 5, lane = tid & 31;
    int d0 = lane * 4;

    for (int e = warp; e < E; e += 8) {
        int cnt = ecnt[e];
        const float* wq = Wq + (size_t)e * D * HD;
        for (int base = 0; base < cnt; base += 8) {
            int nsl = min(8, cnt - base);
            int slot[8]; int xoff[8];
#pragma unroll
            for (int j = 0; j < 8; j++) {
                int s = elist[e * QTW + base + (j < nsl ? j : 0)];
                slot[j] = s;
                xoff[j] = (s >> 3) * XS_STRIDE;
            }
            float acc[8][4] = {};
#pragma unroll 4
            for (int k = 0; k < D; k++) {
                float4 w = *reinterpret_cast<const float4*>(wq + (size_t)k * HD + d0);
#pragma unroll
                for (int j = 0; j < 8; j++) {
                    float xv = xs[xoff[j] + k];
                    acc[j][0] += xv * w.x; acc[j][1] += xv * w.y;
                    acc[j][2] += xv * w.z; acc[j][3] += xv * w.w;
                }
            }
            for (int j = 0; j < nsl; j++) {
                int s = slot[j];
                int gt = token0 + (s >> 3);
                int h  = s & 7;
                float4 o = make_float4(acc[j][0], acc[j][1], acc[j][2], acc[j][3]);
                *reinterpret_cast<float4*>(g_q + (((size_t)gt * H + h) * HD) + d0) = o;
            }
        }
    }
}

// ---------------------------------------------------------------------------
// Kernel 4: flash attention, 3xTF32 mma (error-compensated)
// block = 256 threads (8 warps), q-tile 128 rows, KV-tile 64
// ---------------------------------------------------------------------------
constexpr int QT = 128;
constexpr int KT = 64;
constexpr int QS_STRIDE = 132;   // Qs [row][hd]
constexpr int KS_STRIDE = 72;    // Ks [hd][kv]   (K^T)
constexpr int VS_STRIDE = 136;   // Vs [kv][hd]
constexpr int PS_STRIDE = 68;    // Ps [row][kv]

__global__ __launch_bounds__(256, 1) void attn_kernel()
{
    extern __shared__ float sm[];
    float* Qs = sm;                        // QT * 132
    float* Ks = Qs + QT * QS_STRIDE;       // HD * 72
    float* Vs = Ks + HD * KS_STRIDE;       // KT * 136
    float* Ps = Vs + KT * VS_STRIDE;       // QT * 68

    int tid  = threadIdx.x;
    int warp = tid >> 5, lane = tid & 31;
    int g = lane >> 2, tg = lane & 3;
    int n0 = blockIdx.x * QT;
    int h  = blockIdx.y;
    int b  = blockIdx.z;
    int bN0 = b * N;
    const float scale = 0.08838834764831845f;   // 1/sqrt(128)

    // load Q (pre-scaled) once
    for (int idx = tid; idx < QT * (HD / 4); idx += 256) {
        int r = idx >> 5, kq = (idx & 31) * 4;
        float4 qv = *reinterpret_cast<const float4*>(
            g_q + (((size_t)(bN0 + n0 + r)) * H + h) * HD + kq);
        qv.x *= scale; qv.y *= scale; qv.z *= scale; qv.w *= scale;
        *reinterpret_cast<float4*>(Qs + r * QS_STRIDE + kq) = qv;
    }

    const int r_a = warp * 16 + g;
    const int r_b = r_a + 8;

    float o[16][4];
#pragma unroll
    for (int nc = 0; nc < 16; nc++)
#pragma unroll
        for (int j = 0; j < 4; j++) o[nc][j] = 0.f;
    float m_a = -1e30f, m_b = -1e30f, l_a = 0.f, l_b = 0.f;

    for (int m0 = 0; m0 < N; m0 += KT) {
        __syncthreads();   // prev tile consumed (also covers initial Q load)
        // K^T tile: Ks[k][m]
        for (int idx = tid; idx < HD * (KT / 4); idx += 256) {
            int k = idx >> 4, mq = (idx & 15) * 4;
            *reinterpret_cast<float4*>(Ks + k * KS_STRIDE + mq) =
                *reinterpret_cast<const float4*>(g_kT + (size_t)k * BN_TOK + bN0 + m0 + mq);
        }
        // V tile: Vs[m][hd]
        for (int idx = tid; idx < KT * (HD / 4); idx += 256) {
            int mr = idx >> 5, kq = (idx & 31) * 4;
            *reinterpret_cast<float4*>(Vs + mr * VS_STRIDE + kq) =
                *reinterpret_cast<const float4*>(g_v + ((size_t)(bN0 + m0 + mr)) * HD + kq);
        }
        __syncthreads();

        // ---- S = Q K^T : 16 x 64 per warp, 3xtf32 ----
        float sc[8][4];
#pragma unroll
        for (int nc = 0; nc < 8; nc++)
#pragma unroll
            for (int j = 0; j < 4; j++) sc[nc][j] = 0.f;

#pragma unroll
        for (int ks = 0; ks < 16; ks++) {
            const float* qa0 = Qs + r_a * QS_STRIDE + 8 * ks + tg;
            const float* qa1 = Qs + r_b * QS_STRIDE + 8 * ks + tg;
            float a_raw[4] = { qa0[0], qa1[0], qa0[4], qa1[4] };
            uint32_t ah[4], al[4];
            split4(a_raw, ah, al);
            const float* kb0 = Ks + (8 * ks + tg) * KS_STRIDE + g;
            const float* kb1 = kb0 + 4 * KS_STRIDE;
#pragma unroll
            for (int nc = 0; nc < 8; nc++) {
                uint32_t bh[2], bl[2];
                split2(kb0[8 * nc], kb1[8 * nc], bh, bl);
                mma3(sc[nc], ah, al, bh, bl);
            }
        }

        // ---- online softmax ----
        float lm_a = -1e30f, lm_b = -1e30f;
#pragma unroll
        for (int nc = 0; nc < 8; nc++) {
            lm_a = fmaxf(lm_a, fmaxf(sc[nc][0], sc[nc][1]));
            lm_b = fmaxf(lm_b, fmaxf(sc[nc][2], sc[nc][3]));
        }
#pragma unroll
        for (int off = 1; off <= 2; off <<= 1) {
            lm_a = fmaxf(lm_a, __shfl_xor_sync(0xffffffffu, lm_a, off));
            lm_b = fmaxf(lm_b, __shfl_xor_sync(0xffffffffu, lm_b, off));
        }
        float mn_a = fmaxf(m_a, lm_a), mn_b = fmaxf(m_b, lm_b);
        float al_a = __expf(m_a - mn_a), al_b = __expf(m_b - mn_b);
        m_a = mn_a; m_b = mn_b;

        float rs_a = 0.f, rs_b = 0.f;
#pragma unroll
        for (int nc = 0; nc < 8; nc++) {
            float p0 = __expf(sc[nc][0] - mn_a);
            float p1 = __expf(sc[nc][1] - mn_a);
            float p2 = __expf(sc[nc][2] - mn_b);
            float p3 = __expf(sc[nc][3] - mn_b);
            rs_a += p0 + p1; rs_b += p2 + p3;
            *reinterpret_cast<float2*>(Ps + r_a * PS_STRIDE + 8 * nc + 2 * tg) = make_float2(p0, p1);
            *reinterpret_cast<float2*>(Ps + r_b * PS_STRIDE + 8 * nc + 2 * tg) = make_float2(p2, p3);
        }
#pragma unroll
        for (int off = 1; off <= 2; off <<= 1) {
            rs_a += __shfl_xor_sync(0xffffffffu, rs_a, off);
            rs_b += __shfl_xor_sync(0xffffffffu, rs_b, off);
        }
        l_a = l_a * al_a + rs_a;
        l_b = l_b * al_b + rs_b;
#pragma unroll
        for (int nc = 0; nc < 16; nc++) {
            o[nc][0] *= al_a; o[nc][1] *= al_a;
            o[nc][2] *= al_b; o[nc][3] *= al_b;
        }

        // ---- O += P V : 3xtf32, per-warp-private Ps, no sync needed ----
#pragma unroll
        for (int ks = 0; ks < 8; ks++) {
            const float* pa0 = Ps + r_a * PS_STRIDE + 8 * ks + tg;
            const float* pa1 = Ps + r_b * PS_STRIDE + 8 * ks + tg;
            float a_raw[4] = { pa0[0], pa1[0], pa0[4], pa1[4] };
            uint32_t ah[4], al[4];
            split4(a_raw, ah, al);
            const float* vb0 = Vs + (8 * ks + tg) * VS_STRIDE + g;
            const float* vb1 = vb0 + 4 * VS_STRIDE;
#pragma unroll
            for (int nc = 0; nc < 16; nc++) {
                uint32_t bh[2], bl[2];
                split2(vb0[8 * nc], vb1[8 * nc], bh, bl);
                mma3(o[nc], ah, al, bh, bl);
            }
        }
    }

    float inv_a = 1.f / l_a, inv_b = 1.f / l_b;
    float* dsta = g_attno + (((size_t)(bN0 + n0 + r_a)) * H + h) * HD;
    float* dstb = g_attno + (((size_t)(bN0 + n0 + r_b)) * H + h) * HD;
#pragma unroll
    for (int nc = 0; nc < 16; nc++) {
        *reinterpret_cast<float2*>(dsta + 8 * nc + 2 * tg) =
            make_float2(o[nc][0] * inv_a, o[nc][1] * inv_a);
        *reinterpret_cast<float2*>(dstb + 8 * nc + 2 * tg) =
            make_float2(o[nc][2] * inv_b, o[nc][3] * inv_b);
    }
}

// ---------------------------------------------------------------------------
// Kernel 5: combine
// ---------------------------------------------------------------------------
constexpr int CTW = 16;

__global__ __launch_bounds__(256) void combine_kernel(
    const float* __restrict__ Wo, float* __restrict__ y)
{
    extern __shared__ float sm[];
    float* outs    = sm;                          // [128][132]
    float* ys      = outs + 128 * 132;            // [16][1024]
    float* gates_s = ys + CTW * D;                // 128
    int*   ecnt    = (int*)(gates_s + 128);       // E
    int*   elist   = ecnt + E;                    // E * 16

    int tid = threadIdx.x;
    int token0 = blockIdx.x * CTW;
    if (tid < E) ecnt[tid] = 0;
    __syncthreads();

    if (tid < CTW * H) {
        gates_s[tid] = g_gates[token0 * H + tid];
        int e = g_topi[token0 * H + tid];
        int pos = atomicAdd(&ecnt[e], 1);
        elist[e * CTW + pos] = tid;
    }
    for (int idx = tid; idx < 128 * 32; idx += 256) {
        int s = idx >> 5, kq = (idx & 31) << 2;
        *reinterpret_cast<float4*>(outs + s * 132 + kq) =
            *reinterpret_cast<const float4*>(g_attno + ((size_t)token0 * H + s) * HD + kq);
    }
    for (int idx = tid; idx < CTW * D; idx += 256) ys[idx] = 0.f;
    __syncthreads();

    int c0 = tid * 4;
    for (int e = 0; e < E; e++) {
        int cnt = ecnt[e];
        if (cnt == 0) continue;
        const float* wo = Wo + (size_t)e * HD * D;
        for (int base = 0; base < cnt; base += 8) {
            int nsl = min(8, cnt - base);
            int slot[8]; int soff[8];
#pragma unroll
            for (int j = 0; j < 8; j++) {
                int s = elist[e * CTW + base + (j < nsl ? j : 0)];
                slot[j] = s;
                soff[j] = s * 132;
            }
            float acc[8][4] = {};
#pragma unroll 4
            for (int k = 0; k < HD; k++) {
                float4 w = *reinterpret_cast<const float4*>(wo + (size_t)k * D + c0);
#pragma unroll
                for (int j = 0; j < 8; j++) {
                    float a = outs[soff[j] + k];
                    acc[j][0] += a * w.x; acc[j][1] += a * w.y;
                    acc[j][2] += a * w.z; acc[j][3] += a * w.w;
                }
            }
            for (int j = 0; j < nsl; j++) {
                int s = slot[j];
                float gt = gates_s[s];
                float* yp = ys + (s >> 3) * D + c0;
                yp[0] += gt * acc[j][0]; yp[1] += gt * acc[j][1];
                yp[2] += gt * acc[j][2]; yp[3] += gt * acc[j][3];
            }
        }
    }
    __syncthreads();

    for (int idx = tid; idx < CTW * (D / 4); idx += 256) {
        int tok = idx >> 8, cq = (idx & 255) << 2;
        *reinterpret_cast<float4*>(y + (size_t)(token0 + tok) * D + cq) =
            *reinterpret_cast<const float4*>(ys + tok * D + cq);
    }
}

// ---------------------------------------------------------------------------
// Kernel 6: finalize aux loss
// ---------------------------------------------------------------------------
__global__ void aux_final_kernel(float* __restrict__ out) {
    if (threadIdx.x == 0) {
        const float inv_bn = 1.0f / (float)BN_TOK;
        float sw = 0.f;
        for (int e = 0; e < E; e++)
            sw += (g_aux[e] * inv_bn) * (g_aux[E + e] * inv_bn);
        float aux = 0.1f * (float)E * sw + 0.001f * (g_aux[2 * E] * inv_bn);
        out[(size_t)BN_TOK * D] = aux;
    }
}

// ---------------------------------------------------------------------------
// Launch
// ---------------------------------------------------------------------------
extern "C" void kernel_launch(void* const* d_in, const int* in_sizes, int n_in,
                              void* d_out, int out_size)
{
    const float* x    = (const float*)d_in[0];
    const int* task_bh = (const int*)d_in[1];
    const float* Wg   = (const float*)d_in[2];
    const float* Wq   = (const float*)d_in[3];
    const float* Wo   = (const float*)d_in[4];
    const float* Wkv  = (const float*)d_in[5];
    const float* bkv  = (const float*)d_in[6];
    float* out = (float*)d_out;

    const int q_smem    = (QTW * XS_STRIDE) * 4 + (E + E * QTW) * 4;
    const int attn_smem = (QT * QS_STRIDE + HD * KS_STRIDE + KT * VS_STRIDE + QT * PS_STRIDE) * 4;
    const int comb_smem = (128 * 132 + CTW * D + 128) * 4 + (E + E * CTW) * 4;

    cudaFuncSetAttribute(q_kernel,       cudaFuncAttributeMaxDynamicSharedMemorySize, q_smem);
    cudaFuncSetAttribute(attn_kernel,    cudaFuncAttributeMaxDynamicSharedMemorySize, attn_smem);
    cudaFuncSetAttribute(combine_kernel, cudaFuncAttributeMaxDynamicSharedMemorySize, comb_smem);

    init_aux_kernel<<<1, 64>>>();
    gating_kernel<<<BN_TOK / 8, 256>>>(x, task_bh, Wg);
    kv_kernel<<<dim3(BN_TOK / 64, (2 * HD) / 64), 256>>>(x, Wkv, bkv);
    q_kernel<<<BN_TOK / QTW, 256, q_smem>>>(x, Wq);
    attn_kernel<<<dim3(N / QT, H, B), 256, attn_smem>>>();
    combine_kernel<<<BN_TOK / CTW, 256, comb_smem>>>(Wo, out);
    aux_final_kernel<<<1, 32>>>(out);
}

// round 4
// speedup vs baseline: 2.3756x; 1.9526x over previous
#include <cuda_runtime.h>
#include <math.h>
#include <stdint.h>

// ---------------------------------------------------------------------------
// Problem constants
// ---------------------------------------------------------------------------
constexpr int B    = 4;
constexpr int N    = 2048;
constexpr int D    = 1024;
constexpr int E    = 24;
constexpr int H    = 8;
constexpr int HD   = 128;
constexpr int BN_TOK = B * N;          // 8192 tokens
constexpr int NSLOT  = BN_TOK * H;     // 65536 (token,slot) pairs

// Grouped-GEMM tiling
constexpr int TQ = 128;                // rows per expert tile
constexpr int NT_MAX = NSLOT / TQ + E; // 536 max tiles

// ---------------------------------------------------------------------------
// Scratch (device globals — no allocations allowed)
// ---------------------------------------------------------------------------
__device__ float g_kT[HD * BN_TOK];            // 4 MB  K^T: [hd][token]
__device__ float g_v[BN_TOK * HD];             // 4 MB
__device__ float g_q[NSLOT * HD];              // 32 MB  [slot][hd], slot=token*8+h
__device__ float g_attno[NSLOT * HD];          // 32 MB
__device__ float g_ws[(size_t)NSLOT * D];      // 268 MB combine scratch [slot][D]
__device__ int   g_topi[NSLOT];
__device__ float g_gates[NSLOT];
__device__ float g_aux[2 * E + 1];
// expert bucketing
__device__ int g_ecnt[E];
__device__ int g_eoff[E + 1];
__device__ int g_ecursor[E];
__device__ int g_slots[NSLOT];
__device__ int g_tile_e[NT_MAX];
__device__ int g_tile_r0[NT_MAX];
__device__ int g_ntiles;

// ---------------------------------------------------------------------------
// tf32 mma helpers (3xTF32 error-compensated path)
// ---------------------------------------------------------------------------
__device__ __forceinline__ void mma_tf32(float* d, const uint32_t* a, const uint32_t* b) {
    asm volatile(
        "mma.sync.aligned.m16n8k8.row.col.f32.tf32.tf32.f32 "
        "{%0,%1,%2,%3}, {%4,%5,%6,%7}, {%8,%9}, {%0,%1,%2,%3};\n"
        : "+f"(d[0]), "+f"(d[1]), "+f"(d[2]), "+f"(d[3])
        : "r"(a[0]), "r"(a[1]), "r"(a[2]), "r"(a[3]), "r"(b[0]), "r"(b[1]));
}
__device__ __forceinline__ uint32_t fu(float x) { return __float_as_uint(x); }
__device__ __forceinline__ float tf32_hi(float x) {
    uint32_t u;
    asm("cvt.rna.tf32.f32 %0, %1;" : "=r"(u) : "f"(x));
    return __uint_as_float(u);
}
__device__ __forceinline__ void split4(const float* a, uint32_t* ah, uint32_t* al) {
#pragma unroll
    for (int j = 0; j < 4; j++) {
        float h = tf32_hi(a[j]);
        ah[j] = fu(h);
        al[j] = fu(a[j] - h);
    }
}
__device__ __forceinline__ void split2(float b0, float b1, uint32_t* bh, uint32_t* bl) {
    float h0 = tf32_hi(b0), h1 = tf32_hi(b1);
    bh[0] = fu(h0); bh[1] = fu(h1);
    bl[0] = fu(b0 - h0); bl[1] = fu(b1 - h1);
}
__device__ __forceinline__ void mma3(float* d, const uint32_t* ah, const uint32_t* al,
                                     const uint32_t* bh, const uint32_t* bl) {
    mma_tf32(d, al, bh);
    mma_tf32(d, ah, bl);
    mma_tf32(d, ah, bh);
}

// ---------------------------------------------------------------------------
// Kernel 0: zero aux + expert histogram
// ---------------------------------------------------------------------------
__global__ void init_aux_kernel() {
    int tid = threadIdx.x;
    if (tid < 2 * E + 1) g_aux[tid] = 0.f;
    if (tid < E) g_ecnt[tid] = 0;
}

// ---------------------------------------------------------------------------
// Kernel 1: gating — logits, softmax, top-8, gates, aux partials, histogram
// ---------------------------------------------------------------------------
__global__ __launch_bounds__(256) void gating_kernel(
    const float* __restrict__ x, const int* __restrict__ task_bh,
    const float* __restrict__ Wg)
{
    __shared__ float s_aux[2 * E + 1];
    __shared__ int   s_ecnt[E];
    int tid = threadIdx.x;
    if (tid < 2 * E + 1) s_aux[tid] = 0.f;
    if (tid < E) s_ecnt[tid] = 0;
    __syncthreads();

    int warp = tid >> 5, lane = tid & 31;
    int t = blockIdx.x * 8 + warp;
    int b = t >> 11;
    int task = task_bh[b];
    const float* xrow = x + (size_t)t * D;
    const float* wg   = Wg + (size_t)task * D * E;

    float acc[E];
#pragma unroll
    for (int e = 0; e < E; e++) acc[e] = 0.f;

    for (int i = lane; i < D; i += 32) {
        float xv = xrow[i];
        const float4* w4 = reinterpret_cast<const float4*>(wg + (size_t)i * E);
#pragma unroll
        for (int j = 0; j < 6; j++) {
            float4 v = w4[j];
            acc[4*j+0] += xv * v.x; acc[4*j+1] += xv * v.y;
            acc[4*j+2] += xv * v.z; acc[4*j+3] += xv * v.w;
        }
    }
#pragma unroll
    for (int e = 0; e < E; e++) {
#pragma unroll
        for (int off = 16; off >= 1; off >>= 1)
            acc[e] += __shfl_xor_sync(0xffffffffu, acc[e], off);
    }
    float mx = acc[0];
#pragma unroll
    for (int e = 1; e < E; e++) mx = fmaxf(mx, acc[e]);
    float p[E]; float s = 0.f;
#pragma unroll
    for (int e = 0; e < E; e++) { p[e] = __expf(acc[e] - mx); s += p[e]; }
    float inv_s = 1.f / s;
    float lse = mx + __logf(s);

    if (lane < E) atomicAdd(&s_aux[E + lane], p[lane] * inv_s);
    if (lane == 0) {
        atomicAdd(&s_aux[2 * E], lse * lse);
        float tv[H]; int ti[H]; float gsum = 0.f;
#pragma unroll
        for (int h = 0; h < H; h++) {
            float best = -1.f; int bi = 0;
#pragma unroll
            for (int e = 0; e < E; e++)
                if (p[e] > best) { best = p[e]; bi = e; }
            tv[h] = best * inv_s; ti[h] = bi; p[bi] = -2.f;
            gsum += tv[h];
            atomicAdd(&s_aux[bi], 1.0f);
            atomicAdd(&s_ecnt[bi], 1);
        }
        float ig = 1.f / gsum;
#pragma unroll
        for (int h = 0; h < H; h++) {
            g_topi[t * H + h]  = ti[h];
            g_gates[t * H + h] = tv[h] * ig;
        }
    }
    __syncthreads();
    if (tid < 2 * E + 1) atomicAdd(&g_aux[tid], s_aux[tid]);
    if (tid < E) atomicAdd(&g_ecnt[tid], s_ecnt[tid]);
}

// ---------------------------------------------------------------------------
// Kernel 2: serial scan over experts → offsets + tile table
// ---------------------------------------------------------------------------
__global__ void scan_kernel() {
    if (threadIdx.x == 0) {
        int off = 0, nt = 0;
        for (int e = 0; e < E; e++) {
            g_eoff[e] = off;
            g_ecursor[e] = 0;
            int c = g_ecnt[e];
            for (int r = 0; r < c; r += TQ) {
                g_tile_e[nt]  = e;
                g_tile_r0[nt] = off + r;
                nt++;
            }
            off += c;
        }
        g_eoff[E] = off;
        g_ntiles = nt;
    }
}

// ---------------------------------------------------------------------------
// Kernel 3: scatter slot ids into expert buckets
// ---------------------------------------------------------------------------
__global__ void scatter_kernel() {
    int i = blockIdx.x * 256 + threadIdx.x;
    int e = g_topi[i];
    int pos = atomicAdd(&g_ecursor[e], 1);
    g_slots[g_eoff[e] + pos] = i;
}

// ---------------------------------------------------------------------------
// Kernel 4: kv = x @ Wkv + bkv  → g_kT (transposed), g_v
// ---------------------------------------------------------------------------
__global__ __launch_bounds__(256) void kv_kernel(
    const float* __restrict__ x, const float* __restrict__ Wkv,
    const float* __restrict__ bkv)
{
    __shared__ float As[64][17];
    __shared__ float Bs[16][64];
    int tid = threadIdx.x;
    int tx = tid & 15, ty = tid >> 4;
    int t0 = blockIdx.x * 64;
    int n0 = blockIdx.y * 64;

    float acc[4][4] = {};

    for (int k0 = 0; k0 < D; k0 += 16) {
#pragma unroll
        for (int i = 0; i < 4; i++) {
            int idx = tid + i * 256;
            int r = idx >> 4, kk = idx & 15;
            As[r][kk] = x[(size_t)(t0 + r) * D + k0 + kk];
        }
#pragma unroll
        for (int i = 0; i < 4; i++) {
            int idx = tid + i * 256;
            int kr = idx >> 6, nn = idx & 63;
            Bs[kr][nn] = Wkv[(size_t)(k0 + kr) * (2 * HD) + n0 + nn];
        }
        __syncthreads();
#pragma unroll
        for (int kk = 0; kk < 16; kk++) {
            float a[4];
#pragma unroll
            for (int i = 0; i < 4; i++) a[i] = As[ty * 4 + i][kk];
            float4 bv = *reinterpret_cast<const float4*>(&Bs[kk][tx * 4]);
            float bb[4] = {bv.x, bv.y, bv.z, bv.w};
#pragma unroll
            for (int i = 0; i < 4; i++)
#pragma unroll
                for (int j = 0; j < 4; j++)
                    acc[i][j] += a[i] * bb[j];
        }
        __syncthreads();
    }
#pragma unroll
    for (int i = 0; i < 4; i++) {
        int t = t0 + ty * 4 + i;
#pragma unroll
        for (int j = 0; j < 4; j++) {
            int c = n0 + tx * 4 + j;
            float v = acc[i][j] + bkv[c];
            if (c < HD) g_kT[(size_t)c * BN_TOK + t] = v;
            else        g_v[(size_t)t * HD + (c - HD)] = v;
        }
    }
}

// ---------------------------------------------------------------------------
// Kernel 5: grouped q GEMM — per expert tile: q[slot] = x[token] @ Wq[e]
// CTA: 128 rows x 128 cols (HD), K = D in chunks of 32, 3xTF32 mma
// ---------------------------------------------------------------------------
constexpr int GBK = 32;
constexpr int AS_STR = 36;    // 4g+tg bank map → conflict-free A fragments
constexpr int BS_STR = 136;   // 8tg+g bank map → conflict-free B fragments

__global__ __launch_bounds__(256, 2) void qgemm_kernel(
    const float* __restrict__ x, const float* __restrict__ Wq)
{
    __shared__ float As[TQ * AS_STR];
    __shared__ float Bs[GBK * BS_STR];
    __shared__ int   s_tok[TQ];
    __shared__ int   s_slot[TQ];

    int t = blockIdx.x;
    if (t >= g_ntiles) return;
    int e = g_tile_e[t], r0 = g_tile_r0[t];
    int rend = g_eoff[e + 1];
    int tid = threadIdx.x;

    if (tid < TQ) {
        int gr = r0 + tid;
        if (gr >= rend) gr = r0;          // padded rows duplicate row0 (not written back)
        int s = g_slots[gr];
        s_slot[tid] = s;
        s_tok[tid]  = s >> 3;
    }
    __syncthreads();

    int warp = tid >> 5, lane = tid & 31;
    int g = lane >> 2, tg = lane & 3;
    int r_a = warp * 16 + g, r_b = r_a + 8;
    const float* wq = Wq + (size_t)e * D * HD;

    float acc[16][4] = {};

    for (int k0 = 0; k0 < D; k0 += GBK) {
#pragma unroll
        for (int i = 0; i < 4; i++) {          // A: 128x32 gathered
            int f4 = tid + i * 256;
            int r = f4 >> 3, c = (f4 & 7) * 4;
            *reinterpret_cast<float4*>(As + r * AS_STR + c) =
                *reinterpret_cast<const float4*>(x + (size_t)s_tok[r] * D + k0 + c);
        }
#pragma unroll
        for (int i = 0; i < 4; i++) {          // B: 32x128
            int f4 = tid + i * 256;
            int kr = f4 >> 5, c = (f4 & 31) * 4;
            *reinterpret_cast<float4*>(Bs + kr * BS_STR + c) =
                *reinterpret_cast<const float4*>(wq + (size_t)(k0 + kr) * HD + c);
        }
        __syncthreads();
#pragma unroll
        for (int ks = 0; ks < 4; ks++) {
            int krow = 8 * ks + tg;
            float a_raw[4] = { As[r_a * AS_STR + krow], As[r_b * AS_STR + krow],
                               As[r_a * AS_STR + krow + 4], As[r_b * AS_STR + krow + 4] };
            uint32_t ah[4], al[4];
            split4(a_raw, ah, al);
            const float* b0p = Bs + krow * BS_STR + g;
            const float* b1p = b0p + 4 * BS_STR;
#pragma unroll
            for (int nc = 0; nc < 16; nc++) {
                uint32_t bh[2], bl[2];
                split2(b0p[8 * nc], b1p[8 * nc], bh, bl);
                mma3(acc[nc], ah, al, bh, bl);
            }
        }
        __syncthreads();
    }

    bool va = (r0 + r_a < rend), vb = (r0 + r_b < rend);
    float* da = g_q + (size_t)s_slot[r_a] * HD;
    float* db = g_q + (size_t)s_slot[r_b] * HD;
#pragma unroll
    for (int nc = 0; nc < 16; nc++) {
        int c = 8 * nc + 2 * tg;
        if (va) *reinterpret_cast<float2*>(da + c) = make_float2(acc[nc][0], acc[nc][1]);
        if (vb) *reinterpret_cast<float2*>(db + c) = make_float2(acc[nc][2], acc[nc][3]);
    }
}

// ---------------------------------------------------------------------------
// Kernel 6: flash attention, 3xTF32 mma (unchanged from round 3)
// ---------------------------------------------------------------------------
constexpr int QT = 128;
constexpr int KT = 64;
constexpr int QS_STRIDE = 132;
constexpr int KS_STRIDE = 72;
constexpr int VS_STRIDE = 136;
constexpr int PS_STRIDE = 68;

__global__ __launch_bounds__(256, 1) void attn_kernel()
{
    extern __shared__ float sm[];
    float* Qs = sm;
    float* Ks = Qs + QT * QS_STRIDE;
    float* Vs = Ks + HD * KS_STRIDE;
    float* Ps = Vs + KT * VS_STRIDE;

    int tid  = threadIdx.x;
    int warp = tid >> 5, lane = tid & 31;
    int g = lane >> 2, tg = lane & 3;
    int n0 = blockIdx.x * QT;
    int h  = blockIdx.y;
    int b  = blockIdx.z;
    int bN0 = b * N;
    const float scale = 0.08838834764831845f;

    for (int idx = tid; idx < QT * (HD / 4); idx += 256) {
        int r = idx >> 5, kq = (idx & 31) * 4;
        float4 qv = *reinterpret_cast<const float4*>(
            g_q + (((size_t)(bN0 + n0 + r)) * H + h) * HD + kq);
        qv.x *= scale; qv.y *= scale; qv.z *= scale; qv.w *= scale;
        *reinterpret_cast<float4*>(Qs + r * QS_STRIDE + kq) = qv;
    }

    const int r_a = warp * 16 + g;
    const int r_b = r_a + 8;

    float o[16][4];
#pragma unroll
    for (int nc = 0; nc < 16; nc++)
#pragma unroll
        for (int j = 0; j < 4; j++) o[nc][j] = 0.f;
    float m_a = -1e30f, m_b = -1e30f, l_a = 0.f, l_b = 0.f;

    for (int m0 = 0; m0 < N; m0 += KT) {
        __syncthreads();
        for (int idx = tid; idx < HD * (KT / 4); idx += 256) {
            int k = idx >> 4, mq = (idx & 15) * 4;
            *reinterpret_cast<float4*>(Ks + k * KS_STRIDE + mq) =
                *reinterpret_cast<const float4*>(g_kT + (size_t)k * BN_TOK + bN0 + m0 + mq);
        }
        for (int idx = tid; idx < KT * (HD / 4); idx += 256) {
            int mr = idx >> 5, kq = (idx & 31) * 4;
            *reinterpret_cast<float4*>(Vs + mr * VS_STRIDE + kq) =
                *reinterpret_cast<const float4*>(g_v + ((size_t)(bN0 + m0 + mr)) * HD + kq);
        }
        __syncthreads();

        float sc[8][4];
#pragma unroll
        for (int nc = 0; nc < 8; nc++)
#pragma unroll
            for (int j = 0; j < 4; j++) sc[nc][j] = 0.f;

#pragma unroll
        for (int ks = 0; ks < 16; ks++) {
            const float* qa0 = Qs + r_a * QS_STRIDE + 8 * ks + tg;
            const float* qa1 = Qs + r_b * QS_STRIDE + 8 * ks + tg;
            float a_raw[4] = { qa0[0], qa1[0], qa0[4], qa1[4] };
            uint32_t ah[4], al[4];
            split4(a_raw, ah, al);
            const float* kb0 = Ks + (8 * ks + tg) * KS_STRIDE + g;
            const float* kb1 = kb0 + 4 * KS_STRIDE;
#pragma unroll
            for (int nc = 0; nc < 8; nc++) {
                uint32_t bh[2], bl[2];
                split2(kb0[8 * nc], kb1[8 * nc], bh, bl);
                mma3(sc[nc], ah, al, bh, bl);
            }
        }

        float lm_a = -1e30f, lm_b = -1e30f;
#pragma unroll
        for (int nc = 0; nc < 8; nc++) {
            lm_a = fmaxf(lm_a, fmaxf(sc[nc][0], sc[nc][1]));
            lm_b = fmaxf(lm_b, fmaxf(sc[nc][2], sc[nc][3]));
        }
#pragma unroll
        for (int off = 1; off <= 2; off <<= 1) {
            lm_a = fmaxf(lm_a, __shfl_xor_sync(0xffffffffu, lm_a, off));
            lm_b = fmaxf(lm_b, __shfl_xor_sync(0xffffffffu, lm_b, off));
        }
        float mn_a = fmaxf(m_a, lm_a), mn_b = fmaxf(m_b, lm_b);
        float al_a = __expf(m_a - mn_a), al_b = __expf(m_b - mn_b);
        m_a = mn_a; m_b = mn_b;

        float rs_a = 0.f, rs_b = 0.f;
#pragma unroll
        for (int nc = 0; nc < 8; nc++) {
            float p0 = __expf(sc[nc][0] - mn_a);
            float p1 = __expf(sc[nc][1] - mn_a);
            float p2 = __expf(sc[nc][2] - mn_b);
            float p3 = __expf(sc[nc][3] - mn_b);
            rs_a += p0 + p1; rs_b += p2 + p3;
            *reinterpret_cast<float2*>(Ps + r_a * PS_STRIDE + 8 * nc + 2 * tg) = make_float2(p0, p1);
            *reinterpret_cast<float2*>(Ps + r_b * PS_STRIDE + 8 * nc + 2 * tg) = make_float2(p2, p3);
        }
#pragma unroll
        for (int off = 1; off <= 2; off <<= 1) {
            rs_a += __shfl_xor_sync(0xffffffffu, rs_a, off);
            rs_b += __shfl_xor_sync(0xffffffffu, rs_b, off);
        }
        l_a = l_a * al_a + rs_a;
        l_b = l_b * al_b + rs_b;
#pragma unroll
        for (int nc = 0; nc < 16; nc++) {
            o[nc][0] *= al_a; o[nc][1] *= al_a;
            o[nc][2] *= al_b; o[nc][3] *= al_b;
        }

#pragma unroll
        for (int ks = 0; ks < 8; ks++) {
            const float* pa0 = Ps + r_a * PS_STRIDE + 8 * ks + tg;
            const float* pa1 = Ps + r_b * PS_STRIDE + 8 * ks + tg;
            float a_raw[4] = { pa0[0], pa1[0], pa0[4], pa1[4] };
            uint32_t ah[4], al[4];
            split4(a_raw, ah, al);
            const float* vb0 = Vs + (8 * ks + tg) * VS_STRIDE + g;
            const float* vb1 = vb0 + 4 * VS_STRIDE;
#pragma unroll
            for (int nc = 0; nc < 16; nc++) {
                uint32_t bh[2], bl[2];
                split2(vb0[8 * nc], vb1[8 * nc], bh, bl);
                mma3(o[nc], ah, al, bh, bl);
            }
        }
    }

    float inv_a = 1.f / l_a, inv_b = 1.f / l_b;
    float* dsta = g_attno + (((size_t)(bN0 + n0 + r_a)) * H + h) * HD;
    float* dstb = g_attno + (((size_t)(bN0 + n0 + r_b)) * H + h) * HD;
#pragma unroll
    for (int nc = 0; nc < 16; nc++) {
        *reinterpret_cast<float2*>(dsta + 8 * nc + 2 * tg) =
            make_float2(o[nc][0] * inv_a, o[nc][1] * inv_a);
        *reinterpret_cast<float2*>(dstb + 8 * nc + 2 * tg) =
            make_float2(o[nc][2] * inv_b, o[nc][3] * inv_b);
    }
}

// ---------------------------------------------------------------------------
// Kernel 7: grouped combine GEMM — ws[slot] = gate * (attn_out[slot] @ Wo[e])
// CTA: 128 rows x 128 cols (of D), K = HD in 4 chunks of 32
// ---------------------------------------------------------------------------
__global__ __launch_bounds__(256, 2) void cgemm_kernel(const float* __restrict__ Wo)
{
    __shared__ float As[TQ * AS_STR];
    __shared__ float Bs[GBK * BS_STR];
    __shared__ int   s_slot[TQ];
    __shared__ float s_gate[TQ];

    int t = blockIdx.x;
    if (t >= g_ntiles) return;
    int n0 = blockIdx.y * 128;
    int e = g_tile_e[t], r0 = g_tile_r0[t];
    int rend = g_eoff[e + 1];
    int tid = threadIdx.x;

    if (tid < TQ) {
        int gr = r0 + tid;
        if (gr >= rend) gr = r0;
        int s = g_slots[gr];
        s_slot[tid] = s;
        s_gate[tid] = g_gates[s];
    }
    __syncthreads();

    int warp = tid >> 5, lane = tid & 31;
    int g = lane >> 2, tg = lane & 3;
    int r_a = warp * 16 + g, r_b = r_a + 8;
    const float* wo = Wo + (size_t)e * HD * D;

    float acc[16][4] = {};

    for (int k0 = 0; k0 < HD; k0 += GBK) {
#pragma unroll
        for (int i = 0; i < 4; i++) {          // A: 128x32 from attn out
            int f4 = tid + i * 256;
            int r = f4 >> 3, c = (f4 & 7) * 4;
            *reinterpret_cast<float4*>(As + r * AS_STR + c) =
                *reinterpret_cast<const float4*>(g_attno + (size_t)s_slot[r] * HD + k0 + c);
        }
#pragma unroll
        for (int i = 0; i < 4; i++) {          // B: 32x128 slice of Wo
            int f4 = tid + i * 256;
            int kr = f4 >> 5, c = (f4 & 31) * 4;
            *reinterpret_cast<float4*>(Bs + kr * BS_STR + c) =
                *reinterpret_cast<const float4*>(wo + (size_t)(k0 + kr) * D + n0 + c);
        }
        __syncthreads();
#pragma unroll
        for (int ks = 0; ks < 4; ks++) {
            int krow = 8 * ks + tg;
            float a_raw[4] = { As[r_a * AS_STR + krow], As[r_b * AS_STR + krow],
                               As[r_a * AS_STR + krow + 4], As[r_b * AS_STR + krow + 4] };
            uint32_t ah[4], al[4];
            split4(a_raw, ah, al);
            const float* b0p = Bs + krow * BS_STR + g;
            const float* b1p = b0p + 4 * BS_STR;
#pragma unroll
            for (int nc = 0; nc < 16; nc++) {
                uint32_t bh[2], bl[2];
                split2(b0p[8 * nc], b1p[8 * nc], bh, bl);
                mma3(acc[nc], ah, al, bh, bl);
            }
        }
        __syncthreads();
    }

    bool va = (r0 + r_a < rend), vb = (r0 + r_b < rend);
    float ga = s_gate[r_a], gb = s_gate[r_b];
    float* da = g_ws + (size_t)s_slot[r_a] * D + n0;
    float* db = g_ws + (size_t)s_slot[r_b] * D + n0;
#pragma unroll
    for (int nc = 0; nc < 16; nc++) {
        int c = 8 * nc + 2 * tg;
        if (va) *reinterpret_cast<float2*>(da + c) = make_float2(acc[nc][0] * ga, acc[nc][1] * ga);
        if (vb) *reinterpret_cast<float2*>(db + c) = make_float2(acc[nc][2] * gb, acc[nc][3] * gb);
    }
}

// ---------------------------------------------------------------------------
// Kernel 8: reduce 8 slot rows per token → y
// ---------------------------------------------------------------------------
__global__ __launch_bounds__(256) void reduce_kernel(float* __restrict__ y)
{
    int t = blockIdx.x;
    int c = threadIdx.x * 4;
    float4 s = make_float4(0.f, 0.f, 0.f, 0.f);
#pragma unroll
    for (int h = 0; h < H; h++) {
        float4 v = *reinterpret_cast<const float4*>(g_ws + ((size_t)(t * H + h)) * D + c);
        s.x += v.x; s.y += v.y; s.z += v.z; s.w += v.w;
    }
    *reinterpret_cast<float4*>(y + (size_t)t * D + c) = s;
}

// ---------------------------------------------------------------------------
// Kernel 9: finalize aux loss
// ---------------------------------------------------------------------------
__global__ void aux_final_kernel(float* __restrict__ out) {
    if (threadIdx.x == 0) {
        const float inv_bn = 1.0f / (float)BN_TOK;
        float sw = 0.f;
        for (int e = 0; e < E; e++)
            sw += (g_aux[e] * inv_bn) * (g_aux[E + e] * inv_bn);
        float aux = 0.1f * (float)E * sw + 0.001f * (g_aux[2 * E] * inv_bn);
        out[(size_t)BN_TOK * D] = aux;
    }
}

// ---------------------------------------------------------------------------
// Launch
// ---------------------------------------------------------------------------
extern "C" void kernel_launch(void* const* d_in, const int* in_sizes, int n_in,
                              void* d_out, int out_size)
{
    const float* x    = (const float*)d_in[0];
    const int* task_bh = (const int*)d_in[1];
    const float* Wg   = (const float*)d_in[2];
    const float* Wq   = (const float*)d_in[3];
    const float* Wo   = (const float*)d_in[4];
    const float* Wkv  = (const float*)d_in[5];
    const float* bkv  = (const float*)d_in[6];
    float* out = (float*)d_out;

    const int attn_smem = (QT * QS_STRIDE + HD * KS_STRIDE + KT * VS_STRIDE + QT * PS_STRIDE) * 4;
    cudaFuncSetAttribute(attn_kernel, cudaFuncAttributeMaxDynamicSharedMemorySize, attn_smem);

    init_aux_kernel<<<1, 64>>>();
    gating_kernel<<<BN_TOK / 8, 256>>>(x, task_bh, Wg);
    scan_kernel<<<1, 32>>>();
    scatter_kernel<<<NSLOT / 256, 256>>>();
    kv_kernel<<<dim3(BN_TOK / 64, (2 * HD) / 64), 256>>>(x, Wkv, bkv);
    qgemm_kernel<<<NT_MAX, 256>>>(x, Wq);
    attn_kernel<<<dim3(N / QT, H, B), 256, attn_smem>>>();
    cgemm_kernel<<<dim3(NT_MAX, 8), 256>>>(Wo);
    reduce_kernel<<<BN_TOK, 256>>>(out);
    aux_final_kernel<<<1, 32>>>(out);
}

// round 5
// speedup vs baseline: 3.0163x; 1.2697x over previous
#include <cuda_runtime.h>
#include <math.h>
#include <stdint.h>

// ---------------------------------------------------------------------------
// Problem constants
// ---------------------------------------------------------------------------
constexpr int B    = 4;
constexpr int N    = 2048;
constexpr int D    = 1024;
constexpr int E    = 24;
constexpr int H    = 8;
constexpr int HD   = 128;
constexpr int BN_TOK = B * N;          // 8192 tokens
constexpr int NSLOT  = BN_TOK * H;     // 65536 (token,slot) pairs

// Grouped-GEMM tiling
constexpr int TQ = 128;                // rows per expert tile
constexpr int NT_MAX = NSLOT / TQ + E; // 536 max tiles

// ---------------------------------------------------------------------------
// Scratch (device globals — no allocations allowed)
// ---------------------------------------------------------------------------
__device__ float g_kT[HD * BN_TOK];            // 4 MB  K^T: [hd][token]
__device__ float g_v[BN_TOK * HD];             // 4 MB
__device__ float g_q[NSLOT * HD];              // 32 MB  [slot][hd], slot=token*8+h
__device__ float g_attno[NSLOT * HD];          // 32 MB
__device__ float g_ws[(size_t)NSLOT * D];      // 268 MB combine scratch [slot][D]
__device__ int   g_topi[NSLOT];
__device__ float g_gates[NSLOT];
__device__ float g_aux[2 * E + 1];
// expert bucketing
__device__ int g_ecnt[E];
__device__ int g_eoff[E + 1];
__device__ int g_ecursor[E];
__device__ int g_slots[NSLOT];
__device__ int g_tile_e[NT_MAX];
__device__ int g_tile_r0[NT_MAX];
__device__ int g_ntiles;

// ---------------------------------------------------------------------------
// tf32 mma helpers
// ---------------------------------------------------------------------------
__device__ __forceinline__ void mma_tf32(float* d, const uint32_t* a, const uint32_t* b) {
    asm volatile(
        "mma.sync.aligned.m16n8k8.row.col.f32.tf32.tf32.f32 "
        "{%0,%1,%2,%3}, {%4,%5,%6,%7}, {%8,%9}, {%0,%1,%2,%3};\n"
        : "+f"(d[0]), "+f"(d[1]), "+f"(d[2]), "+f"(d[3])
        : "r"(a[0]), "r"(a[1]), "r"(a[2]), "r"(a[3]), "r"(b[0]), "r"(b[1]));
}
__device__ __forceinline__ uint32_t fu(float x) { return __float_as_uint(x); }
__device__ __forceinline__ float tf32_hi(float x) {
    uint32_t u;
    asm("cvt.rna.tf32.f32 %0, %1;" : "=r"(u) : "f"(x));
    return __uint_as_float(u);
}
__device__ __forceinline__ void split4(const float* a, uint32_t* ah, uint32_t* al) {
#pragma unroll
    for (int j = 0; j < 4; j++) {
        float h = tf32_hi(a[j]);
        ah[j] = fu(h);
        al[j] = fu(a[j] - h);
    }
}
__device__ __forceinline__ void split2(float b0, float b1, uint32_t* bh, uint32_t* bl) {
    float h0 = tf32_hi(b0), h1 = tf32_hi(b1);
    bh[0] = fu(h0); bh[1] = fu(h1);
    bl[0] = fu(b0 - h0); bl[1] = fu(b1 - h1);
}
__device__ __forceinline__ void mma3(float* d, const uint32_t* ah, const uint32_t* al,
                                     const uint32_t* bh, const uint32_t* bl) {
    mma_tf32(d, al, bh);
    mma_tf32(d, ah, bl);
    mma_tf32(d, ah, bh);
}

// ---------------------------------------------------------------------------
// Kernel 0: zero aux + expert histogram
// ---------------------------------------------------------------------------
__global__ void init_aux_kernel() {
    int tid = threadIdx.x;
    if (tid < 2 * E + 1) g_aux[tid] = 0.f;
    if (tid < E) g_ecnt[tid] = 0;
}

// ---------------------------------------------------------------------------
// Kernel 1: gating
// ---------------------------------------------------------------------------
__global__ __launch_bounds__(256) void gating_kernel(
    const float* __restrict__ x, const int* __restrict__ task_bh,
    const float* __restrict__ Wg)
{
    __shared__ float s_aux[2 * E + 1];
    __shared__ int   s_ecnt[E];
    int tid = threadIdx.x;
    if (tid < 2 * E + 1) s_aux[tid] = 0.f;
    if (tid < E) s_ecnt[tid] = 0;
    __syncthreads();

    int warp = tid >> 5, lane = tid & 31;
    int t = blockIdx.x * 8 + warp;
    int b = t >> 11;
    int task = task_bh[b];
    const float* xrow = x + (size_t)t * D;
    const float* wg   = Wg + (size_t)task * D * E;

    float acc[E];
#pragma unroll
    for (int e = 0; e < E; e++) acc[e] = 0.f;

    for (int i = lane; i < D; i += 32) {
        float xv = xrow[i];
        const float4* w4 = reinterpret_cast<const float4*>(wg + (size_t)i * E);
#pragma unroll
        for (int j = 0; j < 6; j++) {
            float4 v = w4[j];
            acc[4*j+0] += xv * v.x; acc[4*j+1] += xv * v.y;
            acc[4*j+2] += xv * v.z; acc[4*j+3] += xv * v.w;
        }
    }
#pragma unroll
    for (int e = 0; e < E; e++) {
#pragma unroll
        for (int off = 16; off >= 1; off >>= 1)
            acc[e] += __shfl_xor_sync(0xffffffffu, acc[e], off);
    }
    float mx = acc[0];
#pragma unroll
    for (int e = 1; e < E; e++) mx = fmaxf(mx, acc[e]);
    float p[E]; float s = 0.f;
#pragma unroll
    for (int e = 0; e < E; e++) { p[e] = __expf(acc[e] - mx); s += p[e]; }
    float inv_s = 1.f / s;
    float lse = mx + __logf(s);

    if (lane < E) atomicAdd(&s_aux[E + lane], p[lane] * inv_s);
    if (lane == 0) {
        atomicAdd(&s_aux[2 * E], lse * lse);
        float tv[H]; int ti[H]; float gsum = 0.f;
#pragma unroll
        for (int h = 0; h < H; h++) {
            float best = -1.f; int bi = 0;
#pragma unroll
            for (int e = 0; e < E; e++)
                if (p[e] > best) { best = p[e]; bi = e; }
            tv[h] = best * inv_s; ti[h] = bi; p[bi] = -2.f;
            gsum += tv[h];
            atomicAdd(&s_aux[bi], 1.0f);
            atomicAdd(&s_ecnt[bi], 1);
        }
        float ig = 1.f / gsum;
#pragma unroll
        for (int h = 0; h < H; h++) {
            g_topi[t * H + h]  = ti[h];
            g_gates[t * H + h] = tv[h] * ig;
        }
    }
    __syncthreads();
    if (tid < 2 * E + 1) atomicAdd(&g_aux[tid], s_aux[tid]);
    if (tid < E) atomicAdd(&g_ecnt[tid], s_ecnt[tid]);
}

// ---------------------------------------------------------------------------
// Kernel 2: serial scan over experts → offsets + tile table
// ---------------------------------------------------------------------------
__global__ void scan_kernel() {
    if (threadIdx.x == 0) {
        int off = 0, nt = 0;
        for (int e = 0; e < E; e++) {
            g_eoff[e] = off;
            g_ecursor[e] = 0;
            int c = g_ecnt[e];
            for (int r = 0; r < c; r += TQ) {
                g_tile_e[nt]  = e;
                g_tile_r0[nt] = off + r;
                nt++;
            }
            off += c;
        }
        g_eoff[E] = off;
        g_ntiles = nt;
    }
}

// ---------------------------------------------------------------------------
// Kernel 3: scatter slot ids into expert buckets
// ---------------------------------------------------------------------------
__global__ void scatter_kernel() {
    int i = blockIdx.x * 256 + threadIdx.x;
    int e = g_topi[i];
    int pos = atomicAdd(&g_ecursor[e], 1);
    g_slots[g_eoff[e] + pos] = i;
}

// ---------------------------------------------------------------------------
// Kernel 4: kv = x @ Wkv + bkv  → g_kT (transposed), g_v
// ---------------------------------------------------------------------------
__global__ __launch_bounds__(256) void kv_kernel(
    const float* __restrict__ x, const float* __restrict__ Wkv,
    const float* __restrict__ bkv)
{
    __shared__ float As[64][17];
    __shared__ float Bs[16][64];
    int tid = threadIdx.x;
    int tx = tid & 15, ty = tid >> 4;
    int t0 = blockIdx.x * 64;
    int n0 = blockIdx.y * 64;

    float acc[4][4] = {};

    for (int k0 = 0; k0 < D; k0 += 16) {
#pragma unroll
        for (int i = 0; i < 4; i++) {
            int idx = tid + i * 256;
            int r = idx >> 4, kk = idx & 15;
            As[r][kk] = x[(size_t)(t0 + r) * D + k0 + kk];
        }
#pragma unroll
        for (int i = 0; i < 4; i++) {
            int idx = tid + i * 256;
            int kr = idx >> 6, nn = idx & 63;
            Bs[kr][nn] = Wkv[(size_t)(k0 + kr) * (2 * HD) + n0 + nn];
        }
        __syncthreads();
#pragma unroll
        for (int kk = 0; kk < 16; kk++) {
            float a[4];
#pragma unroll
            for (int i = 0; i < 4; i++) a[i] = As[ty * 4 + i][kk];
            float4 bv = *reinterpret_cast<const float4*>(&Bs[kk][tx * 4]);
            float bb[4] = {bv.x, bv.y, bv.z, bv.w};
#pragma unroll
            for (int i = 0; i < 4; i++)
#pragma unroll
                for (int j = 0; j < 4; j++)
                    acc[i][j] += a[i] * bb[j];
        }
        __syncthreads();
    }
#pragma unroll
    for (int i = 0; i < 4; i++) {
        int t = t0 + ty * 4 + i;
#pragma unroll
        for (int j = 0; j < 4; j++) {
            int c = n0 + tx * 4 + j;
            float v = acc[i][j] + bkv[c];
            if (c < HD) g_kT[(size_t)c * BN_TOK + t] = v;
            else        g_v[(size_t)t * HD + (c - HD)] = v;
        }
    }
}

// ---------------------------------------------------------------------------
// Kernel 5: grouped q GEMM — 3xTF32 (feeds exp; keep compensated)
// ---------------------------------------------------------------------------
constexpr int GBK = 32;
constexpr int AS_STR = 36;
constexpr int BS_STR = 136;

__global__ __launch_bounds__(256, 2) void qgemm_kernel(
    const float* __restrict__ x, const float* __restrict__ Wq)
{
    __shared__ float As[TQ * AS_STR];
    __shared__ float Bs[GBK * BS_STR];
    __shared__ int   s_tok[TQ];
    __shared__ int   s_slot[TQ];

    int t = blockIdx.x;
    if (t >= g_ntiles) return;
    int e = g_tile_e[t], r0 = g_tile_r0[t];
    int rend = g_eoff[e + 1];
    int tid = threadIdx.x;

    if (tid < TQ) {
        int gr = r0 + tid;
        if (gr >= rend) gr = r0;
        int s = g_slots[gr];
        s_slot[tid] = s;
        s_tok[tid]  = s >> 3;
    }
    __syncthreads();

    int warp = tid >> 5, lane = tid & 31;
    int g = lane >> 2, tg = lane & 3;
    int r_a = warp * 16 + g, r_b = r_a + 8;
    const float* wq = Wq + (size_t)e * D * HD;

    float acc[16][4] = {};

    for (int k0 = 0; k0 < D; k0 += GBK) {
#pragma unroll
        for (int i = 0; i < 4; i++) {
            int f4 = tid + i * 256;
            int r = f4 >> 3, c = (f4 & 7) * 4;
            *reinterpret_cast<float4*>(As + r * AS_STR + c) =
                *reinterpret_cast<const float4*>(x + (size_t)s_tok[r] * D + k0 + c);
        }
#pragma unroll
        for (int i = 0; i < 4; i++) {
            int f4 = tid + i * 256;
            int kr = f4 >> 5, c = (f4 & 31) * 4;
            *reinterpret_cast<float4*>(Bs + kr * BS_STR + c) =
                *reinterpret_cast<const float4*>(wq + (size_t)(k0 + kr) * HD + c);
        }
        __syncthreads();
#pragma unroll
        for (int ks = 0; ks < 4; ks++) {
            int krow = 8 * ks + tg;
            float a_raw[4] = { As[r_a * AS_STR + krow], As[r_b * AS_STR + krow],
                               As[r_a * AS_STR + krow + 4], As[r_b * AS_STR + krow + 4] };
            uint32_t ah[4], al[4];
            split4(a_raw, ah, al);
            const float* b0p = Bs + krow * BS_STR + g;
            const float* b1p = b0p + 4 * BS_STR;
#pragma unroll
            for (int nc = 0; nc < 16; nc++) {
                uint32_t bh[2], bl[2];
                split2(b0p[8 * nc], b1p[8 * nc], bh, bl);
                mma3(acc[nc], ah, al, bh, bl);
            }
        }
        __syncthreads();
    }

    bool va = (r0 + r_a < rend), vb = (r0 + r_b < rend);
    float* da = g_q + (size_t)s_slot[r_a] * HD;
    float* db = g_q + (size_t)s_slot[r_b] * HD;
#pragma unroll
    for (int nc = 0; nc < 16; nc++) {
        int c = 8 * nc + 2 * tg;
        if (va) *reinterpret_cast<float2*>(da + c) = make_float2(acc[nc][0], acc[nc][1]);
        if (vb) *reinterpret_cast<float2*>(db + c) = make_float2(acc[nc][2], acc[nc][3]);
    }
}

// ---------------------------------------------------------------------------
// Kernel 6: flash attention — QK^T 3xTF32 (exp-amplified), PV 1xTF32
// ---------------------------------------------------------------------------
constexpr int QT = 128;
constexpr int KT = 64;
constexpr int QS_STRIDE = 132;
constexpr int KS_STRIDE = 72;
constexpr int VS_STRIDE = 136;
constexpr int PS_STRIDE = 68;

__global__ __launch_bounds__(256, 1) void attn_kernel()
{
    extern __shared__ float sm[];
    float* Qs = sm;
    float* Ks = Qs + QT * QS_STRIDE;
    float* Vs = Ks + HD * KS_STRIDE;
    float* Ps = Vs + KT * VS_STRIDE;

    int tid  = threadIdx.x;
    int warp = tid >> 5, lane = tid & 31;
    int g = lane >> 2, tg = lane & 3;
    int n0 = blockIdx.x * QT;
    int h  = blockIdx.y;
    int b  = blockIdx.z;
    int bN0 = b * N;
    const float scale = 0.08838834764831845f;

    for (int idx = tid; idx < QT * (HD / 4); idx += 256) {
        int r = idx >> 5, kq = (idx & 31) * 4;
        float4 qv = *reinterpret_cast<const float4*>(
            g_q + (((size_t)(bN0 + n0 + r)) * H + h) * HD + kq);
        qv.x *= scale; qv.y *= scale; qv.z *= scale; qv.w *= scale;
        *reinterpret_cast<float4*>(Qs + r * QS_STRIDE + kq) = qv;
    }

    const int r_a = warp * 16 + g;
    const int r_b = r_a + 8;

    float o[16][4];
#pragma unroll
    for (int nc = 0; nc < 16; nc++)
#pragma unroll
        for (int j = 0; j < 4; j++) o[nc][j] = 0.f;
    float m_a = -1e30f, m_b = -1e30f, l_a = 0.f, l_b = 0.f;

    for (int m0 = 0; m0 < N; m0 += KT) {
        __syncthreads();
        for (int idx = tid; idx < HD * (KT / 4); idx += 256) {
            int k = idx >> 4, mq = (idx & 15) * 4;
            *reinterpret_cast<float4*>(Ks + k * KS_STRIDE + mq) =
                *reinterpret_cast<const float4*>(g_kT + (size_t)k * BN_TOK + bN0 + m0 + mq);
        }
        // V tile: cvt.rna to tf32 at load — PV phase runs single-pass
        for (int idx = tid; idx < KT * (HD / 4); idx += 256) {
            int mr = idx >> 5, kq = (idx & 31) * 4;
            float4 vv = *reinterpret_cast<const float4*>(
                g_v + ((size_t)(bN0 + m0 + mr)) * HD + kq);
            vv.x = tf32_hi(vv.x); vv.y = tf32_hi(vv.y);
            vv.z = tf32_hi(vv.z); vv.w = tf32_hi(vv.w);
            *reinterpret_cast<float4*>(Vs + mr * VS_STRIDE + kq) = vv;
        }
        __syncthreads();

        // ---- S = Q K^T : 3xtf32 ----
        float sc[8][4];
#pragma unroll
        for (int nc = 0; nc < 8; nc++)
#pragma unroll
            for (int j = 0; j < 4; j++) sc[nc][j] = 0.f;

#pragma unroll
        for (int ks = 0; ks < 16; ks++) {
            const float* qa0 = Qs + r_a * QS_STRIDE + 8 * ks + tg;
            const float* qa1 = Qs + r_b * QS_STRIDE + 8 * ks + tg;
            float a_raw[4] = { qa0[0], qa1[0], qa0[4], qa1[4] };
            uint32_t ah[4], al[4];
            split4(a_raw, ah, al);
            const float* kb0 = Ks + (8 * ks + tg) * KS_STRIDE + g;
            const float* kb1 = kb0 + 4 * KS_STRIDE;
#pragma unroll
            for (int nc = 0; nc < 8; nc++) {
                uint32_t bh[2], bl[2];
                split2(kb0[8 * nc], kb1[8 * nc], bh, bl);
                mma3(sc[nc], ah, al, bh, bl);
            }
        }

        // ---- online softmax (P stored tf32-rounded) ----
        float lm_a = -1e30f, lm_b = -1e30f;
#pragma unroll
        for (int nc = 0; nc < 8; nc++) {
            lm_a = fmaxf(lm_a, fmaxf(sc[nc][0], sc[nc][1]));
            lm_b = fmaxf(lm_b, fmaxf(sc[nc][2], sc[nc][3]));
        }
#pragma unroll
        for (int off = 1; off <= 2; off <<= 1) {
            lm_a = fmaxf(lm_a, __shfl_xor_sync(0xffffffffu, lm_a, off));
            lm_b = fmaxf(lm_b, __shfl_xor_sync(0xffffffffu, lm_b, off));
        }
        float mn_a = fmaxf(m_a, lm_a), mn_b = fmaxf(m_b, lm_b);
        float al_a = __expf(m_a - mn_a), al_b = __expf(m_b - mn_b);
        m_a = mn_a; m_b = mn_b;

        float rs_a = 0.f, rs_b = 0.f;
#pragma unroll
        for (int nc = 0; nc < 8; nc++) {
            float p0 = __expf(sc[nc][0] - mn_a);
            float p1 = __expf(sc[nc][1] - mn_a);
            float p2 = __expf(sc[nc][2] - mn_b);
            float p3 = __expf(sc[nc][3] - mn_b);
            rs_a += p0 + p1; rs_b += p2 + p3;
            *reinterpret_cast<float2*>(Ps + r_a * PS_STRIDE + 8 * nc + 2 * tg) =
                make_float2(tf32_hi(p0), tf32_hi(p1));
            *reinterpret_cast<float2*>(Ps + r_b * PS_STRIDE + 8 * nc + 2 * tg) =
                make_float2(tf32_hi(p2), tf32_hi(p3));
        }
#pragma unroll
        for (int off = 1; off <= 2; off <<= 1) {
            rs_a += __shfl_xor_sync(0xffffffffu, rs_a, off);
            rs_b += __shfl_xor_sync(0xffffffffu, rs_b, off);
        }
        l_a = l_a * al_a + rs_a;
        l_b = l_b * al_b + rs_b;
#pragma unroll
        for (int nc = 0; nc < 16; nc++) {
            o[nc][0] *= al_a; o[nc][1] *= al_a;
            o[nc][2] *= al_b; o[nc][3] *= al_b;
        }

        // ---- O += P V : single-pass tf32 (operands pre-cvt'd) ----
#pragma unroll
        for (int ks = 0; ks < 8; ks++) {
            const float* pa0 = Ps + r_a * PS_STRIDE + 8 * ks + tg;
            const float* pa1 = Ps + r_b * PS_STRIDE + 8 * ks + tg;
            uint32_t a[4] = { fu(pa0[0]), fu(pa1[0]), fu(pa0[4]), fu(pa1[4]) };
            const float* vb0 = Vs + (8 * ks + tg) * VS_STRIDE + g;
            const float* vb1 = vb0 + 4 * VS_STRIDE;
#pragma unroll
            for (int nc = 0; nc < 16; nc++) {
                uint32_t bb[2] = { fu(vb0[8 * nc]), fu(vb1[8 * nc]) };
                mma_tf32(o[nc], a, bb);
            }
        }
    }

    float inv_a = 1.f / l_a, inv_b = 1.f / l_b;
    float* dsta = g_attno + (((size_t)(bN0 + n0 + r_a)) * H + h) * HD;
    float* dstb = g_attno + (((size_t)(bN0 + n0 + r_b)) * H + h) * HD;
#pragma unroll
    for (int nc = 0; nc < 16; nc++) {
        *reinterpret_cast<float2*>(dsta + 8 * nc + 2 * tg) =
            make_float2(o[nc][0] * inv_a, o[nc][1] * inv_a);
        *reinterpret_cast<float2*>(dstb + 8 * nc + 2 * tg) =
            make_float2(o[nc][2] * inv_b, o[nc][3] * inv_b);
    }
}

// ---------------------------------------------------------------------------
// Kernel 7: grouped combine GEMM — single-pass tf32 (linear output path)
// ---------------------------------------------------------------------------
__global__ __launch_bounds__(256, 2) void cgemm_kernel(const float* __restrict__ Wo)
{
    __shared__ float As[TQ * AS_STR];
    __shared__ float Bs[GBK * BS_STR];
    __shared__ int   s_slot[TQ];
    __shared__ float s_gate[TQ];

    int t = blockIdx.x;
    if (t >= g_ntiles) return;
    int n0 = blockIdx.y * 128;
    int e = g_tile_e[t], r0 = g_tile_r0[t];
    int rend = g_eoff[e + 1];
    int tid = threadIdx.x;

    if (tid < TQ) {
        int gr = r0 + tid;
        if (gr >= rend) gr = r0;
        int s = g_slots[gr];
        s_slot[tid] = s;
        s_gate[tid] = g_gates[s];
    }
    __syncthreads();

    int warp = tid >> 5, lane = tid & 31;
    int g = lane >> 2, tg = lane & 3;
    int r_a = warp * 16 + g, r_b = r_a + 8;
    const float* wo = Wo + (size_t)e * HD * D;

    float acc[16][4] = {};

    for (int k0 = 0; k0 < HD; k0 += GBK) {
#pragma unroll
        for (int i = 0; i < 4; i++) {          // A: attn_out, cvt to tf32 at store
            int f4 = tid + i * 256;
            int r = f4 >> 3, c = (f4 & 7) * 4;
            float4 av = *reinterpret_cast<const float4*>(
                g_attno + (size_t)s_slot[r] * HD + k0 + c);
            av.x = tf32_hi(av.x); av.y = tf32_hi(av.y);
            av.z = tf32_hi(av.z); av.w = tf32_hi(av.w);
            *reinterpret_cast<float4*>(As + r * AS_STR + c) = av;
        }
#pragma unroll
        for (int i = 0; i < 4; i++) {          // B: Wo slice, cvt to tf32 at store
            int f4 = tid + i * 256;
            int kr = f4 >> 5, c = (f4 & 31) * 4;
            float4 bv = *reinterpret_cast<const float4*>(
                wo + (size_t)(k0 + kr) * D + n0 + c);
            bv.x = tf32_hi(bv.x); bv.y = tf32_hi(bv.y);
            bv.z = tf32_hi(bv.z); bv.w = tf32_hi(bv.w);
            *reinterpret_cast<float4*>(Bs + kr * BS_STR + c) = bv;
        }
        __syncthreads();
#pragma unroll
        for (int ks = 0; ks < 4; ks++) {
            int krow = 8 * ks + tg;
            uint32_t a[4] = { fu(As[r_a * AS_STR + krow]), fu(As[r_b * AS_STR + krow]),
                              fu(As[r_a * AS_STR + krow + 4]), fu(As[r_b * AS_STR + krow + 4]) };
            const float* b0p = Bs + krow * BS_STR + g;
            const float* b1p = b0p + 4 * BS_STR;
#pragma unroll
            for (int nc = 0; nc < 16; nc++) {
                uint32_t bb[2] = { fu(b0p[8 * nc]), fu(b1p[8 * nc]) };
                mma_tf32(acc[nc], a, bb);
            }
        }
        __syncthreads();
    }

    bool va = (r0 + r_a < rend), vb = (r0 + r_b < rend);
    float ga = s_gate[r_a], gb = s_gate[r_b];
    float* da = g_ws + (size_t)s_slot[r_a] * D + n0;
    float* db = g_ws + (size_t)s_slot[r_b] * D + n0;
#pragma unroll
    for (int nc = 0; nc < 16; nc++) {
        int c = 8 * nc + 2 * tg;
        if (va) *reinterpret_cast<float2*>(da + c) = make_float2(acc[nc][0] * ga, acc[nc][1] * ga);
        if (vb) *reinterpret_cast<float2*>(db + c) = make_float2(acc[nc][2] * gb, acc[nc][3] * gb);
    }
}

// ---------------------------------------------------------------------------
// Kernel 8: reduce 8 slot rows per token → y
// ---------------------------------------------------------------------------
__global__ __launch_bounds__(256) void reduce_kernel(float* __restrict__ y)
{
    int t = blockIdx.x;
    int c = threadIdx.x * 4;
    float4 s = make_float4(0.f, 0.f, 0.f, 0.f);
#pragma unroll
    for (int h = 0; h < H; h++) {
        float4 v = *reinterpret_cast<const float4*>(g_ws + ((size_t)(t * H + h)) * D + c);
        s.x += v.x; s.y += v.y; s.z += v.z; s.w += v.w;
    }
    *reinterpret_cast<float4*>(y + (size_t)t * D + c) = s;
}

// ---------------------------------------------------------------------------
// Kernel 9: finalize aux loss
// ---------------------------------------------------------------------------
__global__ void aux_final_kernel(float* __restrict__ out) {
    if (threadIdx.x == 0) {
        const float inv_bn = 1.0f / (float)BN_TOK;
        float sw = 0.f;
        for (int e = 0; e < E; e++)
            sw += (g_aux[e] * inv_bn) * (g_aux[E + e] * inv_bn);
        float aux = 0.1f * (float)E * sw + 0.001f * (g_aux[2 * E] * inv_bn);
        out[(size_t)BN_TOK * D] = aux;
    }
}

// ---------------------------------------------------------------------------
// Launch
// ---------------------------------------------------------------------------
extern "C" void kernel_launch(void* const* d_in, const int* in_sizes, int n_in,
                              void* d_out, int out_size)
{
    const float* x    = (const float*)d_in[0];
    const int* task_bh = (const int*)d_in[1];
    const float* Wg   = (const float*)d_in[2];
    const float* Wq   = (const float*)d_in[3];
    const float* Wo   = (const float*)d_in[4];
    const float* Wkv  = (const float*)d_in[5];
    const float* bkv  = (const float*)d_in[6];
    float* out = (float*)d_out;

    const int attn_smem = (QT * QS_STRIDE + HD * KS_STRIDE + KT * VS_STRIDE + QT * PS_STRIDE) * 4;
    cudaFuncSetAttribute(attn_kernel, cudaFuncAttributeMaxDynamicSharedMemorySize, attn_smem);

    init_aux_kernel<<<1, 64>>>();
    gating_kernel<<<BN_TOK / 8, 256>>>(x, task_bh, Wg);
    scan_kernel<<<1, 32>>>();
    scatter_kernel<<<NSLOT / 256, 256>>>();
    kv_kernel<<<dim3(BN_TOK / 64, (2 * HD) / 64), 256>>>(x, Wkv, bkv);
    qgemm_kernel<<<NT_MAX, 256>>>(x, Wq);
    attn_kernel<<<dim3(N / QT, H, B), 256, attn_smem>>>();
    cgemm_kernel<<<dim3(NT_MAX, 8), 256>>>(Wo);
    reduce_kernel<<<BN_TOK, 256>>>(out);
    aux_final_kernel<<<1, 32>>>(out);
}